// round 8
// baseline (speedup 1.0000x reference)
#include <cuda_runtime.h>
#include <cstdint>

// IndexedLinearLayer: out[j] = sum_i W[idx[i], i, j] * x[i] + bias[j]
// x f32[8192], indices int32 OR int64 [8192] (dtype detected at runtime),
// param_index f32[16,8192,2048], bias f32[2048] -> out f32[2048]
//
// R8: cp.async (LDGSTS) 8-deep per-thread smem ring replaces register-resident
// float4 loads. R7 showed DRAM stuck at 51% with regs=64: effective MLP was
// reg-limited to ~3-4. cp.async gives MLP=8/thread with zero dest registers
// (113 KB in flight per SM >> ~30 KB Little's-law requirement). Slots are
// thread-private -> no __syncthreads in the pipeline. v4 RED combine kept
// from R7 (proven win).

#define SIZE_IN    8192
#define SIZE_OUT   2048
#define NUM_Q      16
#define THREADS    256
#define I_PER_BLK  32
#define J_PER_BLK  (THREADS * 4)              // 1024 floats per block
#define J_BLOCKS   (SIZE_OUT / J_PER_BLK)     // 2
#define I_BLOCKS   (SIZE_IN / I_PER_BLK)      // 256
#define STAGES     8

// Decoded indices scratch (no device allocation allowed).
__device__ int g_idx[SIZE_IN];

// Prep: seed out = bias, and decode indices robustly (int32 vs int64).
__global__ __launch_bounds__(THREADS)
void prep_kernel(const void* __restrict__ idx_raw,
                 const float* __restrict__ bias,
                 float* __restrict__ out) {
    __shared__ int s_not64;
    if (threadIdx.x == 0) s_not64 = 0;
    __syncthreads();

    // Probe first 4096 int64-interpreted entries (32 KB: in-bounds for both
    // int32[8192] and int64[8192] buffers). Genuine int64 indices are all in
    // [0,16); int32 data reinterpreted as int64 is out of range w.h.p.
    const long long* p64 = (const long long*)idx_raw;
    int bad = 0;
    for (int k = threadIdx.x; k < SIZE_IN / 2; k += THREADS) {
        long long v = p64[k];
        bad |= (v < 0 || v >= NUM_Q) ? 1 : 0;
    }
    if (bad) s_not64 = 1;       // benign race: all writers store 1
    __syncthreads();

    if (s_not64) {              // int32 indices
        const int* p32 = (const int*)idx_raw;
        for (int k = threadIdx.x; k < SIZE_IN; k += THREADS)
            g_idx[k] = p32[k];
    } else {                    // int64 indices
        for (int k = threadIdx.x; k < SIZE_IN; k += THREADS)
            g_idx[k] = (int)p64[k];
    }

    // Seed output with bias (d_out is poisoned before timing).
    for (int j = threadIdx.x; j < SIZE_OUT; j += THREADS)
        out[j] = bias[j];
}

__device__ __forceinline__ void cp_async16(void* smem_dst, const void* gmem_src) {
    uint32_t dst = (uint32_t)__cvta_generic_to_shared(smem_dst);
    asm volatile("cp.async.cg.shared.global [%0], [%1], 16;\n"
                 :: "r"(dst), "l"(gmem_src) : "memory");
}
__device__ __forceinline__ void cp_commit() {
    asm volatile("cp.async.commit_group;\n" ::: "memory");
}

__global__ __launch_bounds__(THREADS)
void indexed_gemv_kernel(const float* __restrict__ x,
                         const float* __restrict__ W,
                         float* __restrict__ out) {
    __shared__ float        s_x[I_PER_BLK];
    __shared__ const float* s_row[I_PER_BLK];
    __shared__ float4       s_buf[STAGES][THREADS];   // 32 KB ring

    const int t  = threadIdx.x;
    const int i0 = blockIdx.y * I_PER_BLK;

    // Stage the 32 (x, gathered-row-pointer) pairs for this i-chunk.
    if (t < I_PER_BLK) {
        const int i = i0 + t;
        s_x[t] = x[i];
        const int q = g_idx[i];
        s_row[t] = W + (size_t)q * ((size_t)SIZE_IN * SIZE_OUT)
                     + (size_t)i * SIZE_OUT;
    }
    __syncthreads();

    const int j = blockIdx.x * J_PER_BLK + t * 4;

    // Prologue: fill all 8 pipeline stages (8 LDGSTS in flight per thread).
    #pragma unroll
    for (int s = 0; s < STAGES; ++s) {
        cp_async16(&s_buf[s][t], s_row[s] + j);
        cp_commit();
    }

    float4 acc = make_float4(0.f, 0.f, 0.f, 0.f);

    // Main pipeline: wait oldest group, consume own slot, refill same slot.
    #pragma unroll
    for (int k = 0; k < I_PER_BLK - STAGES; ++k) {
        asm volatile("cp.async.wait_group %0;\n" :: "n"(STAGES - 1) : "memory");
        const float4 w  = s_buf[k % STAGES][t];
        const float  xv = s_x[k];
        acc.x = fmaf(w.x, xv, acc.x);
        acc.y = fmaf(w.y, xv, acc.y);
        acc.z = fmaf(w.z, xv, acc.z);
        acc.w = fmaf(w.w, xv, acc.w);
        cp_async16(&s_buf[k % STAGES][t], s_row[k + STAGES] + j);
        cp_commit();
    }

    // Drain: wait for everything, consume the last STAGES slots.
    asm volatile("cp.async.wait_all;\n" ::: "memory");
    #pragma unroll
    for (int k = I_PER_BLK - STAGES; k < I_PER_BLK; ++k) {
        const float4 w  = s_buf[k % STAGES][t];
        const float  xv = s_x[k];
        acc.x = fmaf(w.x, xv, acc.x);
        acc.y = fmaf(w.y, xv, acc.y);
        acc.z = fmaf(w.z, xv, acc.z);
        acc.w = fmaf(w.w, xv, acc.w);
    }

    // Split-K combine: one vectorized no-return reduction per thread
    // (out + j is 16B-aligned; 256 v4-REDs per address — proven OK in R7).
    asm volatile("red.global.add.v4.f32 [%0], {%1, %2, %3, %4};"
                 :: "l"(out + j), "f"(acc.x), "f"(acc.y), "f"(acc.z), "f"(acc.w)
                 : "memory");
}

extern "C" void kernel_launch(void* const* d_in, const int* in_sizes, int n_in,
                              void* d_out, int out_size) {
    // Map buffers by size where unique; x/indices keep metadata order.
    const float* x    = (const float*)d_in[0];
    const void*  idxp = d_in[1];
    const float* W    = (const float*)d_in[2];
    const float* bias = (const float*)d_in[3];
    for (int k = 0; k < n_in; ++k) {
        long long sz = in_sizes[k];
        if (sz == (long long)NUM_Q * SIZE_IN * SIZE_OUT) W    = (const float*)d_in[k];
        else if (sz == SIZE_OUT)                         bias = (const float*)d_in[k];
    }
    float* out = (float*)d_out;

    prep_kernel<<<1, THREADS>>>(idxp, bias, out);

    dim3 grid(J_BLOCKS, I_BLOCKS);  // (2, 256) = 512 CTAs, single wave
    indexed_gemv_kernel<<<grid, THREADS>>>(x, W, out);
}